// round 3
// baseline (speedup 1.0000x reference)
#include <cuda_runtime.h>
#include <math.h>

// Problem constants
#define BB 2
#define HH 8
#define TT 4096
#define DD 64
#define CC 512
#define MM (BB*TT)   // 8192

// Scratch (device globals: allocation-free)
__device__ float g_q[BB*HH*TT*DD];   // [b,h,t,d]
__device__ float g_k[BB*HH*TT*DD];
__device__ float g_v[BB*HH*TT*DD];
__device__ float g_y[BB*TT*CC];      // [b,t,c]  attention output before Wout

// ---------------------------------------------------------------------------
// SGEMM: C[m,o] = sum_c X[m,c] * W[o,c]    (Linear: y = x @ W.T)
// 128x128 tile, BK=8, 256 threads, 8x8 per-thread microtile.
// ---------------------------------------------------------------------------

__global__ __launch_bounds__(256) void gemm_qkv(const float* __restrict__ X,
                                                const float* __restrict__ Wq,
                                                const float* __restrict__ Wk,
                                                const float* __restrict__ Wv)
{
    const float* W   = (blockIdx.z == 0) ? Wq : (blockIdx.z == 1) ? Wk : Wv;
    float*       Out = (blockIdx.z == 0) ? g_q : (blockIdx.z == 1) ? g_k : g_v;

    __shared__ float As[8][128];
    __shared__ float Bs[8][128];

    const int tid = threadIdx.x;
    const int m0 = blockIdx.y * 128, n0 = blockIdx.x * 128;

    const int lr = tid & 127;          // row within tile for loads
    const int lk = (tid >> 7) * 4;     // k offset 0 or 4
    const float* Xg = X + (m0 + lr) * CC + lk;
    const float* Wg = W + (n0 + lr) * CC + lk;

    const int tx = tid & 15, ty = tid >> 4;

    float acc[8][8];
#pragma unroll
    for (int i = 0; i < 8; i++)
#pragma unroll
        for (int j = 0; j < 8; j++) acc[i][j] = 0.f;

    for (int k0 = 0; k0 < CC; k0 += 8) {
        float4 av = *(const float4*)(Xg + k0);
        float4 bv = *(const float4*)(Wg + k0);
        __syncthreads();
        As[lk + 0][lr] = av.x; As[lk + 1][lr] = av.y;
        As[lk + 2][lr] = av.z; As[lk + 3][lr] = av.w;
        Bs[lk + 0][lr] = bv.x; Bs[lk + 1][lr] = bv.y;
        Bs[lk + 2][lr] = bv.z; Bs[lk + 3][lr] = bv.w;
        __syncthreads();
#pragma unroll
        for (int kk = 0; kk < 8; kk++) {
            float a[8], b[8];
            *(float4*)&a[0] = *(const float4*)&As[kk][ty * 8];
            *(float4*)&a[4] = *(const float4*)&As[kk][ty * 8 + 4];
            *(float4*)&b[0] = *(const float4*)&Bs[kk][tx * 8];
            *(float4*)&b[4] = *(const float4*)&Bs[kk][tx * 8 + 4];
#pragma unroll
            for (int i = 0; i < 8; i++)
#pragma unroll
                for (int j = 0; j < 8; j++) acc[i][j] += a[i] * b[j];
        }
    }

    // Epilogue: write into [b,h,t,d] layout. For a fixed tx, the 8 consecutive
    // output features stay inside one head (8 | 64), so h,d0 are per-row consts.
    const int o0 = n0 + tx * 8;
    const int h  = o0 >> 6;
    const int d0 = o0 & 63;
#pragma unroll
    for (int i = 0; i < 8; i++) {
        int m  = m0 + ty * 8 + i;
        int b_ = m >> 12;           // / 4096
        int t  = m & 4095;
        float* op = Out + (((b_ * HH + h) * TT) + t) * DD + d0;
        *(float4*)op       = make_float4(acc[i][0], acc[i][1], acc[i][2], acc[i][3]);
        *(float4*)(op + 4) = make_float4(acc[i][4], acc[i][5], acc[i][6], acc[i][7]);
    }
}

__global__ __launch_bounds__(256) void gemm_out(const float* __restrict__ W,
                                                float* __restrict__ OutP)
{
    __shared__ float As[8][128];
    __shared__ float Bs[8][128];

    const int tid = threadIdx.x;
    const int m0 = blockIdx.y * 128, n0 = blockIdx.x * 128;

    const int lr = tid & 127;
    const int lk = (tid >> 7) * 4;
    const float* Xg = g_y + (m0 + lr) * CC + lk;
    const float* Wg = W + (n0 + lr) * CC + lk;

    const int tx = tid & 15, ty = tid >> 4;

    float acc[8][8];
#pragma unroll
    for (int i = 0; i < 8; i++)
#pragma unroll
        for (int j = 0; j < 8; j++) acc[i][j] = 0.f;

    for (int k0 = 0; k0 < CC; k0 += 8) {
        float4 av = *(const float4*)(Xg + k0);
        float4 bv = *(const float4*)(Wg + k0);
        __syncthreads();
        As[lk + 0][lr] = av.x; As[lk + 1][lr] = av.y;
        As[lk + 2][lr] = av.z; As[lk + 3][lr] = av.w;
        Bs[lk + 0][lr] = bv.x; Bs[lk + 1][lr] = bv.y;
        Bs[lk + 2][lr] = bv.z; Bs[lk + 3][lr] = bv.w;
        __syncthreads();
#pragma unroll
        for (int kk = 0; kk < 8; kk++) {
            float a[8], b[8];
            *(float4*)&a[0] = *(const float4*)&As[kk][ty * 8];
            *(float4*)&a[4] = *(const float4*)&As[kk][ty * 8 + 4];
            *(float4*)&b[0] = *(const float4*)&Bs[kk][tx * 8];
            *(float4*)&b[4] = *(const float4*)&Bs[kk][tx * 8 + 4];
#pragma unroll
            for (int i = 0; i < 8; i++)
#pragma unroll
                for (int j = 0; j < 8; j++) acc[i][j] += a[i] * b[j];
        }
    }

#pragma unroll
    for (int i = 0; i < 8; i++) {
        int m = m0 + ty * 8 + i;
        float* op = OutP + m * CC + n0 + tx * 8;
        *(float4*)op       = make_float4(acc[i][0], acc[i][1], acc[i][2], acc[i][3]);
        *(float4*)(op + 4) = make_float4(acc[i][4], acc[i][5], acc[i][6], acc[i][7]);
    }
}

// ---------------------------------------------------------------------------
// Flash attention: one CTA per (b*h, 64-query tile). 256 threads =
// 64 query rows x 4 lanes. Online softmax over 64-key tiles, causal.
// ---------------------------------------------------------------------------

#define SSTR 68                           // float stride for 64-wide tiles (pad)
#define FLASH_SMEM (4 * 64 * SSTR * (int)sizeof(float))   // 69632 B

__global__ __launch_bounds__(256) void flash_attn()
{
    const int bh    = blockIdx.y;                   // 0..15
    const int qtile = gridDim.x - 1 - blockIdx.x;   // long tiles launch first
    const int q0    = qtile * 64;

    const float* Q = g_q + (size_t)bh * TT * DD;
    const float* K = g_k + (size_t)bh * TT * DD;
    const float* V = g_v + (size_t)bh * TT * DD;

    extern __shared__ float sm[];
    float* Qs = sm;
    float* Ks = Qs + 64 * SSTR;
    float* Vs = Ks + 64 * SSTR;
    float* Ss = Vs + 64 * SSTR;

    const int tid = threadIdx.x;

    // Load Q tile (64 x 64 floats)
    for (int i = tid; i < 64 * 16; i += 256) {
        int r = i >> 4, d4 = i & 15;
        *(float4*)&Qs[r * SSTR + d4 * 4] = *(const float4*)(Q + (q0 + r) * DD + d4 * 4);
    }

    const int q  = tid >> 2;     // query row 0..63
    const int l4 = tid & 3;      // lane within row group
    const int d0 = l4 * 16;      // owned d-chunk for PV/output
    const int qg = q0 + q;       // global query index

    float m_i = -INFINITY, l_i = 0.f;
    float acc[16];
#pragma unroll
    for (int i = 0; i < 16; i++) acc[i] = 0.f;

    const int ntiles = qtile + 1;
    for (int jt = 0; jt < ntiles; jt++) {
        const int j0 = jt * 64;
        __syncthreads();   // protect Ks/Vs/Ss reuse (and Q load on jt==0)

        // Load K, V tiles
        for (int i = tid; i < 64 * 16; i += 256) {
            int r = i >> 4, d4 = i & 15;
            *(float4*)&Ks[r * SSTR + d4 * 4] = *(const float4*)(K + (j0 + r) * DD + d4 * 4);
            *(float4*)&Vs[r * SSTR + d4 * 4] = *(const float4*)(V + (j0 + r) * DD + d4 * 4);
        }
        __syncthreads();

        // ---- scores: this thread does keys j = l4 + 4*jj (16 keys), full 64-dot
        float sc[16];
#pragma unroll
        for (int jj = 0; jj < 16; jj++) sc[jj] = 0.f;
#pragma unroll
        for (int d = 0; d < 64; d += 4) {
            float4 qv = *(const float4*)&Qs[q * SSTR + d];
#pragma unroll
            for (int jj = 0; jj < 16; jj++) {
                float4 kv = *(const float4*)&Ks[(l4 + 4 * jj) * SSTR + d];
                sc[jj] += qv.x * kv.x + qv.y * kv.y + qv.z * kv.z + qv.w * kv.w;
            }
        }
        const bool diag = (jt == ntiles - 1);
#pragma unroll
        for (int jj = 0; jj < 16; jj++) {
            int j = l4 + 4 * jj;
            float s = sc[jj] * 0.125f;                 // 1/sqrt(64)
            if (diag && (j0 + j > qg)) s = -1e30f;     // causal mask
            Ss[q * SSTR + j] = s;
        }
        __syncwarp();   // row group (4 lanes) lives in one warp

        // ---- online softmax: each lane owns contiguous chunk of 16 scores
        float sv[16];
        float mloc = -INFINITY;
#pragma unroll
        for (int i4 = 0; i4 < 4; i4++) {
            float4 t4 = *(const float4*)&Ss[q * SSTR + l4 * 16 + 4 * i4];
            sv[4 * i4 + 0] = t4.x; sv[4 * i4 + 1] = t4.y;
            sv[4 * i4 + 2] = t4.z; sv[4 * i4 + 3] = t4.w;
        }
#pragma unroll
        for (int i = 0; i < 16; i++) mloc = fmaxf(mloc, sv[i]);
        mloc = fmaxf(mloc, __shfl_xor_sync(0xffffffffu, mloc, 1));
        mloc = fmaxf(mloc, __shfl_xor_sync(0xffffffffu, mloc, 2));

        float m_new = fmaxf(m_i, mloc);
        float corr  = __expf(m_i - m_new);
        float psum  = 0.f;
#pragma unroll
        for (int i = 0; i < 16; i++) {
            float p = __expf(sv[i] - m_new);
            psum += p;
            Ss[q * SSTR + l4 * 16 + i] = p;
        }
        psum += __shfl_xor_sync(0xffffffffu, psum, 1);
        psum += __shfl_xor_sync(0xffffffffu, psum, 2);
        l_i = l_i * corr + psum;
        m_i = m_new;
#pragma unroll
        for (int i = 0; i < 16; i++) acc[i] *= corr;
        __syncwarp();

        // ---- PV: acc[dd] += sum_j p[j] * V[j][d0+dd]
#pragma unroll 4
        for (int j = 0; j < 64; j++) {
            float pj = Ss[q * SSTR + j];
#pragma unroll
            for (int dd4 = 0; dd4 < 4; dd4++) {
                float4 vv = *(const float4*)&Vs[j * SSTR + d0 + 4 * dd4];
                acc[4 * dd4 + 0] += pj * vv.x;
                acc[4 * dd4 + 1] += pj * vv.y;
                acc[4 * dd4 + 2] += pj * vv.z;
                acc[4 * dd4 + 3] += pj * vv.w;
            }
        }
    }

    // ---- write normalized output into g_y [b,t,c] with c = h*64 + d
    const float inv = 1.f / l_i;
    const int h  = bh & 7;
    const int b_ = bh >> 3;
    float* yp = g_y + ((size_t)(b_ * TT + qg)) * CC + h * 64 + d0;
#pragma unroll
    for (int dd4 = 0; dd4 < 4; dd4++) {
        *(float4*)(yp + 4 * dd4) = make_float4(acc[4 * dd4 + 0] * inv,
                                               acc[4 * dd4 + 1] * inv,
                                               acc[4 * dd4 + 2] * inv,
                                               acc[4 * dd4 + 3] * inv);
    }
}

// ---------------------------------------------------------------------------

extern "C" void kernel_launch(void* const* d_in, const int* in_sizes, int n_in,
                              void* d_out, int out_size)
{
    const float* x    = (const float*)d_in[0];
    const float* Wq   = (const float*)d_in[1];
    const float* Wk   = (const float*)d_in[2];
    const float* Wv   = (const float*)d_in[3];
    const float* Wout = (const float*)d_in[4];
    float* out = (float*)d_out;

    cudaFuncSetAttribute(flash_attn, cudaFuncAttributeMaxDynamicSharedMemorySize,
                         FLASH_SMEM);

    // QKV projections: grid (N/128, M/128, 3)
    gemm_qkv<<<dim3(CC / 128, MM / 128, 3), 256>>>(x, Wq, Wk, Wv);
    // Attention: grid (T/64 query tiles, B*H)
    flash_attn<<<dim3(TT / 64, BB * HH), 256, FLASH_SMEM>>>();
    // Output projection
    gemm_out<<<dim3(CC / 128, MM / 128), 256>>>(Wout, out);
}

// round 4
// speedup vs baseline: 4.7816x; 4.7816x over previous
#include <cuda_runtime.h>
#include <math.h>
#include <stdint.h>

// Problem constants
#define BB 2
#define HH 8
#define TT 4096
#define DD 64
#define CC 512
#define MM (BB*TT)   // 8192

// Scratch (device globals: allocation-free)
__device__ float g_q[BB*HH*TT*DD];   // [b,h,t,d]
__device__ float g_k[BB*HH*TT*DD];
__device__ float g_v[BB*HH*TT*DD];
__device__ float g_y[BB*TT*CC];      // [b,t,c]  attention output before Wout

// ---------------------------------------------------------------------------
// SGEMM: C[m,o] = sum_c X[m,c] * W[o,c]    (Linear: y = x @ W.T)
// 128x128 tile, BK=8, 256 threads, 8x8 per-thread microtile. (unchanged)
// ---------------------------------------------------------------------------

__global__ __launch_bounds__(256) void gemm_qkv(const float* __restrict__ X,
                                                const float* __restrict__ Wq,
                                                const float* __restrict__ Wk,
                                                const float* __restrict__ Wv)
{
    const float* W   = (blockIdx.z == 0) ? Wq : (blockIdx.z == 1) ? Wk : Wv;
    float*       Out = (blockIdx.z == 0) ? g_q : (blockIdx.z == 1) ? g_k : g_v;

    __shared__ float As[8][128];
    __shared__ float Bs[8][128];

    const int tid = threadIdx.x;
    const int m0 = blockIdx.y * 128, n0 = blockIdx.x * 128;

    const int lr = tid & 127;
    const int lk = (tid >> 7) * 4;
    const float* Xg = X + (m0 + lr) * CC + lk;
    const float* Wg = W + (n0 + lr) * CC + lk;

    const int tx = tid & 15, ty = tid >> 4;

    float acc[8][8];
#pragma unroll
    for (int i = 0; i < 8; i++)
#pragma unroll
        for (int j = 0; j < 8; j++) acc[i][j] = 0.f;

    for (int k0 = 0; k0 < CC; k0 += 8) {
        float4 av = *(const float4*)(Xg + k0);
        float4 bv = *(const float4*)(Wg + k0);
        __syncthreads();
        As[lk + 0][lr] = av.x; As[lk + 1][lr] = av.y;
        As[lk + 2][lr] = av.z; As[lk + 3][lr] = av.w;
        Bs[lk + 0][lr] = bv.x; Bs[lk + 1][lr] = bv.y;
        Bs[lk + 2][lr] = bv.z; Bs[lk + 3][lr] = bv.w;
        __syncthreads();
#pragma unroll
        for (int kk = 0; kk < 8; kk++) {
            float a[8], b[8];
            *(float4*)&a[0] = *(const float4*)&As[kk][ty * 8];
            *(float4*)&a[4] = *(const float4*)&As[kk][ty * 8 + 4];
            *(float4*)&b[0] = *(const float4*)&Bs[kk][tx * 8];
            *(float4*)&b[4] = *(const float4*)&Bs[kk][tx * 8 + 4];
#pragma unroll
            for (int i = 0; i < 8; i++)
#pragma unroll
                for (int j = 0; j < 8; j++) acc[i][j] += a[i] * b[j];
        }
    }

    const int o0 = n0 + tx * 8;
    const int h  = o0 >> 6;
    const int d0 = o0 & 63;
#pragma unroll
    for (int i = 0; i < 8; i++) {
        int m  = m0 + ty * 8 + i;
        int b_ = m >> 12;
        int t  = m & 4095;
        float* op = Out + (((b_ * HH + h) * TT) + t) * DD + d0;
        *(float4*)op       = make_float4(acc[i][0], acc[i][1], acc[i][2], acc[i][3]);
        *(float4*)(op + 4) = make_float4(acc[i][4], acc[i][5], acc[i][6], acc[i][7]);
    }
}

__global__ __launch_bounds__(256) void gemm_out(const float* __restrict__ W,
                                                float* __restrict__ OutP)
{
    __shared__ float As[8][128];
    __shared__ float Bs[8][128];

    const int tid = threadIdx.x;
    const int m0 = blockIdx.y * 128, n0 = blockIdx.x * 128;

    const int lr = tid & 127;
    const int lk = (tid >> 7) * 4;
    const float* Xg = g_y + (m0 + lr) * CC + lk;
    const float* Wg = W + (n0 + lr) * CC + lk;

    const int tx = tid & 15, ty = tid >> 4;

    float acc[8][8];
#pragma unroll
    for (int i = 0; i < 8; i++)
#pragma unroll
        for (int j = 0; j < 8; j++) acc[i][j] = 0.f;

    for (int k0 = 0; k0 < CC; k0 += 8) {
        float4 av = *(const float4*)(Xg + k0);
        float4 bv = *(const float4*)(Wg + k0);
        __syncthreads();
        As[lk + 0][lr] = av.x; As[lk + 1][lr] = av.y;
        As[lk + 2][lr] = av.z; As[lk + 3][lr] = av.w;
        Bs[lk + 0][lr] = bv.x; Bs[lk + 1][lr] = bv.y;
        Bs[lk + 2][lr] = bv.z; Bs[lk + 3][lr] = bv.w;
        __syncthreads();
#pragma unroll
        for (int kk = 0; kk < 8; kk++) {
            float a[8], b[8];
            *(float4*)&a[0] = *(const float4*)&As[kk][ty * 8];
            *(float4*)&a[4] = *(const float4*)&As[kk][ty * 8 + 4];
            *(float4*)&b[0] = *(const float4*)&Bs[kk][tx * 8];
            *(float4*)&b[4] = *(const float4*)&Bs[kk][tx * 8 + 4];
#pragma unroll
            for (int i = 0; i < 8; i++)
#pragma unroll
                for (int j = 0; j < 8; j++) acc[i][j] += a[i] * b[j];
        }
    }

#pragma unroll
    for (int i = 0; i < 8; i++) {
        int m = m0 + ty * 8 + i;
        float* op = OutP + m * CC + n0 + tx * 8;
        *(float4*)op       = make_float4(acc[i][0], acc[i][1], acc[i][2], acc[i][3]);
        *(float4*)(op + 4) = make_float4(acc[i][4], acc[i][5], acc[i][6], acc[i][7]);
    }
}

// ---------------------------------------------------------------------------
// Tensor-core flash attention (tf32 mma.sync m16n8k8).
// CTA = 128 threads = 4 warps; 64-query tile (16 rows/warp); 64-key tiles.
// Smem strides: Q/K/P = 68 floats (frag gathers hit banks 4g+t: conflict-free)
//               V     = 72 floats (frag gathers hit banks 8t+g: conflict-free)
// ---------------------------------------------------------------------------

#define KSTR 68
#define VSTR 72
#define FLASH_SMEM ((3 * 64 * KSTR + 64 * VSTR) * (int)sizeof(uint32_t))  // 70656

__device__ __forceinline__ uint32_t f2tf(float f) {
    uint32_t u;
    asm("cvt.rna.tf32.f32 %0, %1;" : "=r"(u) : "f"(f));
    return u;
}
__device__ __forceinline__ float ex2(float x) {
    float y;
    asm("ex2.approx.ftz.f32 %0, %1;" : "=f"(y) : "f"(x));
    return y;
}
__device__ __forceinline__ void mma_tf32(float c[4],
                                         uint32_t a0, uint32_t a1, uint32_t a2, uint32_t a3,
                                         uint32_t b0, uint32_t b1) {
    asm volatile(
        "mma.sync.aligned.m16n8k8.row.col.f32.tf32.tf32.f32 "
        "{%0,%1,%2,%3}, {%4,%5,%6,%7}, {%8,%9}, {%0,%1,%2,%3};"
        : "+f"(c[0]), "+f"(c[1]), "+f"(c[2]), "+f"(c[3])
        : "r"(a0), "r"(a1), "r"(a2), "r"(a3), "r"(b0), "r"(b1));
}

__global__ __launch_bounds__(128) void flash_tc()
{
    const int bh    = blockIdx.y;                   // 0..15
    const int qtile = gridDim.x - 1 - blockIdx.x;   // long tiles launch first
    const int q0    = qtile * 64;

    const float* Qg = g_q + (size_t)bh * TT * DD;
    const float* Kg = g_k + (size_t)bh * TT * DD;
    const float* Vg = g_v + (size_t)bh * TT * DD;

    extern __shared__ uint32_t smu[];
    uint32_t* Qs = smu;
    uint32_t* Ks = Qs + 64 * KSTR;
    uint32_t* Ps = Ks + 64 * KSTR;
    uint32_t* Vs = Ps + 64 * KSTR;

    const int tid  = threadIdx.x;
    const int w    = tid >> 5;        // warp 0..3 -> query rows w*16..w*16+15
    const int lane = tid & 31;
    const int g    = lane >> 2;       // groupID 0..7
    const int t    = lane & 3;        // threadID_in_group

    // Load + convert Q tile (64x64) to tf32 in smem
    for (int i = tid; i < 1024; i += 128) {
        int r = i >> 4, c4 = (i & 15) * 4;
        float4 v = *(const float4*)(Qg + (q0 + r) * DD + c4);
        uint32_t* p = &Qs[r * KSTR + c4];
        p[0] = f2tf(v.x); p[1] = f2tf(v.y); p[2] = f2tf(v.z); p[3] = f2tf(v.w);
    }

    float m[2] = {-INFINITY, -INFINITY};
    float l[2] = {0.f, 0.f};
    float o[8][4];
#pragma unroll
    for (int dt = 0; dt < 8; dt++)
#pragma unroll
        for (int k = 0; k < 4; k++) o[dt][k] = 0.f;

    const int rowA = w * 16 + g;          // local row in 64-tile
    const int qA   = q0 + rowA;           // global query (row A)
    const float SC = 0.125f * 1.4426950408889634f;   // 1/sqrt(64) * log2(e)

    const int ntiles = qtile + 1;
    for (int jt = 0; jt < ntiles; jt++) {
        const int j0 = jt * 64;
        __syncthreads();   // prior-iter readers done (and Q stores ordered on jt==0)

        // Load + convert K,V tiles
        for (int i = tid; i < 1024; i += 128) {
            int r = i >> 4, c4 = (i & 15) * 4;
            float4 kv = *(const float4*)(Kg + (j0 + r) * DD + c4);
            float4 vv = *(const float4*)(Vg + (j0 + r) * DD + c4);
            uint32_t* pk = &Ks[r * KSTR + c4];
            pk[0] = f2tf(kv.x); pk[1] = f2tf(kv.y); pk[2] = f2tf(kv.z); pk[3] = f2tf(kv.w);
            uint32_t* pv = &Vs[r * VSTR + c4];
            pv[0] = f2tf(vv.x); pv[1] = f2tf(vv.y); pv[2] = f2tf(vv.z); pv[3] = f2tf(vv.w);
        }
        __syncthreads();

        // ---- S = Q K^T : 8 n-tiles (keys), 8 k-steps (d)
        float c[8][4];
#pragma unroll
        for (int nt = 0; nt < 8; nt++)
#pragma unroll
            for (int k = 0; k < 4; k++) c[nt][k] = 0.f;

#pragma unroll
        for (int ks = 0; ks < 8; ks++) {
            uint32_t a0 = Qs[(rowA)     * KSTR + ks * 8 + t];
            uint32_t a1 = Qs[(rowA + 8) * KSTR + ks * 8 + t];
            uint32_t a2 = Qs[(rowA)     * KSTR + ks * 8 + t + 4];
            uint32_t a3 = Qs[(rowA + 8) * KSTR + ks * 8 + t + 4];
#pragma unroll
            for (int nt = 0; nt < 8; nt++) {
                uint32_t b0 = Ks[(nt * 8 + g) * KSTR + ks * 8 + t];
                uint32_t b1 = Ks[(nt * 8 + g) * KSTR + ks * 8 + t + 4];
                mma_tf32(c[nt], a0, a1, a2, a3, b0, b1);
            }
        }

        // ---- softmax (log2 domain), causal mask on diagonal tile
        const bool diag = (jt == qtile);
        float mA = -INFINITY, mB = -INFINITY;
#pragma unroll
        for (int nt = 0; nt < 8; nt++) {
            int j = j0 + nt * 8 + 2 * t;
            float s0 = c[nt][0] * SC, s1 = c[nt][1] * SC;
            float s2 = c[nt][2] * SC, s3 = c[nt][3] * SC;
            if (diag) {
                if (j     > qA)     s0 = -1e30f;
                if (j + 1 > qA)     s1 = -1e30f;
                if (j     > qA + 8) s2 = -1e30f;
                if (j + 1 > qA + 8) s3 = -1e30f;
            }
            c[nt][0] = s0; c[nt][1] = s1; c[nt][2] = s2; c[nt][3] = s3;
            mA = fmaxf(mA, fmaxf(s0, s1));
            mB = fmaxf(mB, fmaxf(s2, s3));
        }
        mA = fmaxf(mA, __shfl_xor_sync(0xffffffffu, mA, 1));
        mA = fmaxf(mA, __shfl_xor_sync(0xffffffffu, mA, 2));
        mB = fmaxf(mB, __shfl_xor_sync(0xffffffffu, mB, 1));
        mB = fmaxf(mB, __shfl_xor_sync(0xffffffffu, mB, 2));

        float mnA = fmaxf(m[0], mA), mnB = fmaxf(m[1], mB);
        float corrA = ex2(m[0] - mnA), corrB = ex2(m[1] - mnB);
        m[0] = mnA; m[1] = mnB;

        float lpA = 0.f, lpB = 0.f;
#pragma unroll
        for (int nt = 0; nt < 8; nt++) {
            float p0 = ex2(c[nt][0] - mnA), p1 = ex2(c[nt][1] - mnA);
            float p2 = ex2(c[nt][2] - mnB), p3 = ex2(c[nt][3] - mnB);
            lpA += p0 + p1;  lpB += p2 + p3;
            uint32_t* pa = &Ps[(rowA)     * KSTR + nt * 8 + 2 * t];
            uint32_t* pb = &Ps[(rowA + 8) * KSTR + nt * 8 + 2 * t];
            pa[0] = f2tf(p0); pa[1] = f2tf(p1);
            pb[0] = f2tf(p2); pb[1] = f2tf(p3);
        }
        l[0] = l[0] * corrA + lpA;
        l[1] = l[1] * corrB + lpB;
#pragma unroll
        for (int dt = 0; dt < 8; dt++) {
            o[dt][0] *= corrA; o[dt][1] *= corrA;
            o[dt][2] *= corrB; o[dt][3] *= corrB;
        }
        __syncwarp();   // P slab is warp-private: warp sync suffices

        // ---- O += P V : k = key (8 steps), n-tiles over d
#pragma unroll
        for (int kt = 0; kt < 8; kt++) {
            uint32_t a0 = Ps[(rowA)     * KSTR + kt * 8 + t];
            uint32_t a1 = Ps[(rowA + 8) * KSTR + kt * 8 + t];
            uint32_t a2 = Ps[(rowA)     * KSTR + kt * 8 + t + 4];
            uint32_t a3 = Ps[(rowA + 8) * KSTR + kt * 8 + t + 4];
#pragma unroll
            for (int dt = 0; dt < 8; dt++) {
                uint32_t b0 = Vs[(kt * 8 + t)     * VSTR + dt * 8 + g];
                uint32_t b1 = Vs[(kt * 8 + t + 4) * VSTR + dt * 8 + g];
                mma_tf32(o[dt], a0, a1, a2, a3, b0, b1);
            }
        }
        // next-iter __syncthreads orders Ps overwrite vs these reads
    }

    // ---- normalize + write to g_y [b,t,c], c = h*64 + d
    float lA = l[0];
    lA += __shfl_xor_sync(0xffffffffu, lA, 1);
    lA += __shfl_xor_sync(0xffffffffu, lA, 2);
    float lB = l[1];
    lB += __shfl_xor_sync(0xffffffffu, lB, 1);
    lB += __shfl_xor_sync(0xffffffffu, lB, 2);
    const float iA = 1.f / lA, iB = 1.f / lB;

    const int h  = bh & 7;
    const int b_ = bh >> 3;
    float* yA = g_y + ((size_t)(b_ * TT + qA))     * CC + h * 64;
    float* yB = g_y + ((size_t)(b_ * TT + qA + 8)) * CC + h * 64;
#pragma unroll
    for (int dt = 0; dt < 8; dt++) {
        *(float2*)(yA + dt * 8 + 2 * t) = make_float2(o[dt][0] * iA, o[dt][1] * iA);
        *(float2*)(yB + dt * 8 + 2 * t) = make_float2(o[dt][2] * iB, o[dt][3] * iB);
    }
}

// ---------------------------------------------------------------------------

extern "C" void kernel_launch(void* const* d_in, const int* in_sizes, int n_in,
                              void* d_out, int out_size)
{
    const float* x    = (const float*)d_in[0];
    const float* Wq   = (const float*)d_in[1];
    const float* Wk   = (const float*)d_in[2];
    const float* Wv   = (const float*)d_in[3];
    const float* Wout = (const float*)d_in[4];
    float* out = (float*)d_out;

    cudaFuncSetAttribute(flash_tc, cudaFuncAttributeMaxDynamicSharedMemorySize,
                         FLASH_SMEM);

    gemm_qkv<<<dim3(CC / 128, MM / 128, 3), 256>>>(x, Wq, Wk, Wv);
    flash_tc<<<dim3(TT / 64, BB * HH), 128, FLASH_SMEM>>>();
    gemm_out<<<dim3(CC / 128, MM / 128), 256>>>(Wout, out);
}

// round 5
// speedup vs baseline: 6.0019x; 1.2552x over previous
#include <cuda_runtime.h>
#include <math.h>
#include <stdint.h>

// Problem constants
#define BB 2
#define HH 8
#define TT 4096
#define DD 64
#define CC 512
#define MM (BB*TT)   // 8192

// Scratch (device globals: allocation-free)
__device__ float g_q[BB*HH*TT*DD];   // [b,h,t,d]
__device__ float g_k[BB*HH*TT*DD];
__device__ float g_v[BB*HH*TT*DD];
__device__ float g_y[BB*TT*CC];      // [b,t,c]  attention output before Wout

// ---------------------------------------------------------------------------
// Common tf32 helpers
// ---------------------------------------------------------------------------

__device__ __forceinline__ uint32_t f2tf(float f) {
    uint32_t u;
    asm("cvt.rna.tf32.f32 %0, %1;" : "=r"(u) : "f"(f));
    return u;
}
__device__ __forceinline__ float ex2(float x) {
    float y;
    asm("ex2.approx.ftz.f32 %0, %1;" : "=f"(y) : "f"(x));
    return y;
}
__device__ __forceinline__ void mma_tf32(float c[4],
                                         uint32_t a0, uint32_t a1, uint32_t a2, uint32_t a3,
                                         uint32_t b0, uint32_t b1) {
    asm volatile(
        "mma.sync.aligned.m16n8k8.row.col.f32.tf32.tf32.f32 "
        "{%0,%1,%2,%3}, {%4,%5,%6,%7}, {%8,%9}, {%0,%1,%2,%3};"
        : "+f"(c[0]), "+f"(c[1]), "+f"(c[2]), "+f"(c[3])
        : "r"(a0), "r"(a1), "r"(a2), "r"(a3), "r"(b0), "r"(b1));
}

// tf32 hi/lo split: hi = rna(x) (fp32-representable), lo = rna(x - hi).
// hi*hi + hi*lo + lo*hi leaves O(2^-22) relative error.
__device__ __forceinline__ void split_tf32(float x, uint32_t& hi, uint32_t& lo) {
    hi = f2tf(x);
    lo = f2tf(x - __uint_as_float(hi));
}

// ---------------------------------------------------------------------------
// Tensor-core split-tf32 GEMM: C[m,o] = sum_c X[m,c] * W[o,c]
// CTA 128x128, BK=32, 256 threads (8 warps, 4x2 warp grid, 32x64 warp tile).
// Smem: Ah/Al/Bh/Bl, u32, row stride 36 (bank = 4g+t: conflict-free frags).
// ---------------------------------------------------------------------------

#define GSTR 36
#define GEMM_SMEM (4 * 128 * GSTR * (int)sizeof(uint32_t))   // 73728 B

// Shared mainloop: fills acc[2][8][4] for this thread.
__device__ __forceinline__ void gemm_mainloop(const float* __restrict__ X,
                                              const float* __restrict__ W,
                                              int m0, int n0,
                                              uint32_t* Ah, uint32_t* Al,
                                              uint32_t* Bh, uint32_t* Bl,
                                              float acc[2][8][4])
{
    const int tid  = threadIdx.x;
    const int w    = tid >> 5;
    const int lane = tid & 31;
    const int g    = lane >> 2;
    const int t    = lane & 3;
    const int wm   = w >> 1;            // 0..3 : rows wm*32..+31
    const int wn   = w & 1;             // 0..1 : cols wn*64..+63

    // loader: thread -> row r = tid>>1, 16 consecutive floats at col (tid&1)*16
    const int lr = tid >> 1;
    const int lc = (tid & 1) * 16;
    const float* Xg = X + (m0 + lr) * CC + lc;
    const float* Wg = W + (n0 + lr) * CC + lc;

#pragma unroll
    for (int mt = 0; mt < 2; mt++)
#pragma unroll
        for (int nt = 0; nt < 8; nt++)
#pragma unroll
            for (int k = 0; k < 4; k++) acc[mt][nt][k] = 0.f;

    for (int k0 = 0; k0 < CC; k0 += 32) {
        float4 av[4], bv[4];
#pragma unroll
        for (int i = 0; i < 4; i++) {
            av[i] = *(const float4*)(Xg + k0 + i * 4);
            bv[i] = *(const float4*)(Wg + k0 + i * 4);
        }
        __syncthreads();   // previous-iter frag reads done
#pragma unroll
        for (int i = 0; i < 4; i++) {
            uint32_t h0,l0,h1,l1,h2,l2,h3,l3;
            split_tf32(av[i].x, h0, l0); split_tf32(av[i].y, h1, l1);
            split_tf32(av[i].z, h2, l2); split_tf32(av[i].w, h3, l3);
            uint32_t* pa = &Ah[lr * GSTR + lc + i * 4];
            uint32_t* qa = &Al[lr * GSTR + lc + i * 4];
            pa[0]=h0; pa[1]=h1; pa[2]=h2; pa[3]=h3;
            qa[0]=l0; qa[1]=l1; qa[2]=l2; qa[3]=l3;
            split_tf32(bv[i].x, h0, l0); split_tf32(bv[i].y, h1, l1);
            split_tf32(bv[i].z, h2, l2); split_tf32(bv[i].w, h3, l3);
            uint32_t* pb = &Bh[lr * GSTR + lc + i * 4];
            uint32_t* qb = &Bl[lr * GSTR + lc + i * 4];
            pb[0]=h0; pb[1]=h1; pb[2]=h2; pb[3]=h3;
            qb[0]=l0; qb[1]=l1; qb[2]=l2; qb[3]=l3;
        }
        __syncthreads();

#pragma unroll
        for (int ks = 0; ks < 4; ks++) {
            const int kb = ks * 8;
            uint32_t ah[2][4], al[2][4];
#pragma unroll
            for (int mt = 0; mt < 2; mt++) {
                int r = wm * 32 + mt * 16 + g;
                ah[mt][0] = Ah[(r)     * GSTR + kb + t];
                ah[mt][1] = Ah[(r + 8) * GSTR + kb + t];
                ah[mt][2] = Ah[(r)     * GSTR + kb + t + 4];
                ah[mt][3] = Ah[(r + 8) * GSTR + kb + t + 4];
                al[mt][0] = Al[(r)     * GSTR + kb + t];
                al[mt][1] = Al[(r + 8) * GSTR + kb + t];
                al[mt][2] = Al[(r)     * GSTR + kb + t + 4];
                al[mt][3] = Al[(r + 8) * GSTR + kb + t + 4];
            }
#pragma unroll
            for (int nt = 0; nt < 8; nt++) {
                int cn = wn * 64 + nt * 8 + g;
                uint32_t bh0 = Bh[cn * GSTR + kb + t];
                uint32_t bh1 = Bh[cn * GSTR + kb + t + 4];
                uint32_t bl0 = Bl[cn * GSTR + kb + t];
                uint32_t bl1 = Bl[cn * GSTR + kb + t + 4];
#pragma unroll
                for (int mt = 0; mt < 2; mt++) {
                    mma_tf32(acc[mt][nt], ah[mt][0], ah[mt][1], ah[mt][2], ah[mt][3], bh0, bh1);
                    mma_tf32(acc[mt][nt], ah[mt][0], ah[mt][1], ah[mt][2], ah[mt][3], bl0, bl1);
                    mma_tf32(acc[mt][nt], al[mt][0], al[mt][1], al[mt][2], al[mt][3], bh0, bh1);
                }
            }
        }
    }
}

// QKV projections, epilogue scatters into [b,h,t,d]
__global__ __launch_bounds__(256, 2) void gemm_qkv_tc(const float* __restrict__ X,
                                                      const float* __restrict__ Wq,
                                                      const float* __restrict__ Wk,
                                                      const float* __restrict__ Wv)
{
    const float* W   = (blockIdx.z == 0) ? Wq : (blockIdx.z == 1) ? Wk : Wv;
    float*       Out = (blockIdx.z == 0) ? g_q : (blockIdx.z == 1) ? g_k : g_v;

    extern __shared__ uint32_t sm[];
    uint32_t* Ah = sm;
    uint32_t* Al = Ah + 128 * GSTR;
    uint32_t* Bh = Al + 128 * GSTR;
    uint32_t* Bl = Bh + 128 * GSTR;

    const int m0 = blockIdx.y * 128, n0 = blockIdx.x * 128;
    float acc[2][8][4];
    gemm_mainloop(X, W, m0, n0, Ah, Al, Bh, Bl, acc);

    const int lane = threadIdx.x & 31;
    const int w    = threadIdx.x >> 5;
    const int g = lane >> 2, t = lane & 3;
    const int wm = w >> 1, wn = w & 1;

#pragma unroll
    for (int mt = 0; mt < 2; mt++) {
        int row = m0 + wm * 32 + mt * 16 + g;
        int b_  = row >> 12;
        int tr  = row & 4095;
#pragma unroll
        for (int nt = 0; nt < 8; nt++) {
            int col = n0 + wn * 64 + nt * 8 + 2 * t;
            int h = col >> 6, d = col & 63;
            float* base = Out + (((size_t)(b_ * HH + h) * TT) + tr) * DD + d;
            *(float2*)base            = make_float2(acc[mt][nt][0], acc[mt][nt][1]);
            *(float2*)(base + 8 * DD) = make_float2(acc[mt][nt][2], acc[mt][nt][3]);
        }
    }
}

// Output projection, plain row-major epilogue
__global__ __launch_bounds__(256, 2) void gemm_out_tc(const float* __restrict__ W,
                                                      float* __restrict__ OutP)
{
    extern __shared__ uint32_t sm[];
    uint32_t* Ah = sm;
    uint32_t* Al = Ah + 128 * GSTR;
    uint32_t* Bh = Al + 128 * GSTR;
    uint32_t* Bl = Bh + 128 * GSTR;

    const int m0 = blockIdx.y * 128, n0 = blockIdx.x * 128;
    float acc[2][8][4];
    gemm_mainloop(g_y, W, m0, n0, Ah, Al, Bh, Bl, acc);

    const int lane = threadIdx.x & 31;
    const int w    = threadIdx.x >> 5;
    const int g = lane >> 2, t = lane & 3;
    const int wm = w >> 1, wn = w & 1;

#pragma unroll
    for (int mt = 0; mt < 2; mt++) {
        int row = m0 + wm * 32 + mt * 16 + g;
#pragma unroll
        for (int nt = 0; nt < 8; nt++) {
            int col = n0 + wn * 64 + nt * 8 + 2 * t;
            float* base = OutP + (size_t)row * CC + col;
            *(float2*)base            = make_float2(acc[mt][nt][0], acc[mt][nt][1]);
            *(float2*)(base + 8 * CC) = make_float2(acc[mt][nt][2], acc[mt][nt][3]);
        }
    }
}

// ---------------------------------------------------------------------------
// Tensor-core flash attention (tf32 mma.sync m16n8k8). Unchanged from R3.
// ---------------------------------------------------------------------------

#define KSTR 68
#define VSTR 72
#define FLASH_SMEM ((3 * 64 * KSTR + 64 * VSTR) * (int)sizeof(uint32_t))  // 70656

__global__ __launch_bounds__(128) void flash_tc()
{
    const int bh    = blockIdx.y;
    const int qtile = gridDim.x - 1 - blockIdx.x;
    const int q0    = qtile * 64;

    const float* Qg = g_q + (size_t)bh * TT * DD;
    const float* Kg = g_k + (size_t)bh * TT * DD;
    const float* Vg = g_v + (size_t)bh * TT * DD;

    extern __shared__ uint32_t smu[];
    uint32_t* Qs = smu;
    uint32_t* Ks = Qs + 64 * KSTR;
    uint32_t* Ps = Ks + 64 * KSTR;
    uint32_t* Vs = Ps + 64 * KSTR;

    const int tid  = threadIdx.x;
    const int w    = tid >> 5;
    const int lane = tid & 31;
    const int g    = lane >> 2;
    const int t    = lane & 3;

    for (int i = tid; i < 1024; i += 128) {
        int r = i >> 4, c4 = (i & 15) * 4;
        float4 v = *(const float4*)(Qg + (q0 + r) * DD + c4);
        uint32_t* p = &Qs[r * KSTR + c4];
        p[0] = f2tf(v.x); p[1] = f2tf(v.y); p[2] = f2tf(v.z); p[3] = f2tf(v.w);
    }

    float m[2] = {-INFINITY, -INFINITY};
    float l[2] = {0.f, 0.f};
    float o[8][4];
#pragma unroll
    for (int dt = 0; dt < 8; dt++)
#pragma unroll
        for (int k = 0; k < 4; k++) o[dt][k] = 0.f;

    const int rowA = w * 16 + g;
    const int qA   = q0 + rowA;
    const float SC = 0.125f * 1.4426950408889634f;

    const int ntiles = qtile + 1;
    for (int jt = 0; jt < ntiles; jt++) {
        const int j0 = jt * 64;
        __syncthreads();

        for (int i = tid; i < 1024; i += 128) {
            int r = i >> 4, c4 = (i & 15) * 4;
            float4 kv = *(const float4*)(Kg + (j0 + r) * DD + c4);
            float4 vv = *(const float4*)(Vg + (j0 + r) * DD + c4);
            uint32_t* pk = &Ks[r * KSTR + c4];
            pk[0] = f2tf(kv.x); pk[1] = f2tf(kv.y); pk[2] = f2tf(kv.z); pk[3] = f2tf(kv.w);
            uint32_t* pv = &Vs[r * VSTR + c4];
            pv[0] = f2tf(vv.x); pv[1] = f2tf(vv.y); pv[2] = f2tf(vv.z); pv[3] = f2tf(vv.w);
        }
        __syncthreads();

        float c[8][4];
#pragma unroll
        for (int nt = 0; nt < 8; nt++)
#pragma unroll
            for (int k = 0; k < 4; k++) c[nt][k] = 0.f;

#pragma unroll
        for (int ks = 0; ks < 8; ks++) {
            uint32_t a0 = Qs[(rowA)     * KSTR + ks * 8 + t];
            uint32_t a1 = Qs[(rowA + 8) * KSTR + ks * 8 + t];
            uint32_t a2 = Qs[(rowA)     * KSTR + ks * 8 + t + 4];
            uint32_t a3 = Qs[(rowA + 8) * KSTR + ks * 8 + t + 4];
#pragma unroll
            for (int nt = 0; nt < 8; nt++) {
                uint32_t b0 = Ks[(nt * 8 + g) * KSTR + ks * 8 + t];
                uint32_t b1 = Ks[(nt * 8 + g) * KSTR + ks * 8 + t + 4];
                mma_tf32(c[nt], a0, a1, a2, a3, b0, b1);
            }
        }

        const bool diag = (jt == qtile);
        float mA = -INFINITY, mB = -INFINITY;
#pragma unroll
        for (int nt = 0; nt < 8; nt++) {
            int j = j0 + nt * 8 + 2 * t;
            float s0 = c[nt][0] * SC, s1 = c[nt][1] * SC;
            float s2 = c[nt][2] * SC, s3 = c[nt][3] * SC;
            if (diag) {
                if (j     > qA)     s0 = -1e30f;
                if (j + 1 > qA)     s1 = -1e30f;
                if (j     > qA + 8) s2 = -1e30f;
                if (j + 1 > qA + 8) s3 = -1e30f;
            }
            c[nt][0] = s0; c[nt][1] = s1; c[nt][2] = s2; c[nt][3] = s3;
            mA = fmaxf(mA, fmaxf(s0, s1));
            mB = fmaxf(mB, fmaxf(s2, s3));
        }
        mA = fmaxf(mA, __shfl_xor_sync(0xffffffffu, mA, 1));
        mA = fmaxf(mA, __shfl_xor_sync(0xffffffffu, mA, 2));
        mB = fmaxf(mB, __shfl_xor_sync(0xffffffffu, mB, 1));
        mB = fmaxf(mB, __shfl_xor_sync(0xffffffffu, mB, 2));

        float mnA = fmaxf(m[0], mA), mnB = fmaxf(m[1], mB);
        float corrA = ex2(m[0] - mnA), corrB = ex2(m[1] - mnB);
        m[0] = mnA; m[1] = mnB;

        float lpA = 0.f, lpB = 0.f;
#pragma unroll
        for (int nt = 0; nt < 8; nt++) {
            float p0 = ex2(c[nt][0] - mnA), p1 = ex2(c[nt][1] - mnA);
            float p2 = ex2(c[nt][2] - mnB), p3 = ex2(c[nt][3] - mnB);
            lpA += p0 + p1;  lpB += p2 + p3;
            uint32_t* pa = &Ps[(rowA)     * KSTR + nt * 8 + 2 * t];
            uint32_t* pb = &Ps[(rowA + 8) * KSTR + nt * 8 + 2 * t];
            pa[0] = f2tf(p0); pa[1] = f2tf(p1);
            pb[0] = f2tf(p2); pb[1] = f2tf(p3);
        }
        l[0] = l[0] * corrA + lpA;
        l[1] = l[1] * corrB + lpB;
#pragma unroll
        for (int dt = 0; dt < 8; dt++) {
            o[dt][0] *= corrA; o[dt][1] *= corrA;
            o[dt][2] *= corrB; o[dt][3] *= corrB;
        }
        __syncwarp();

#pragma unroll
        for (int kt = 0; kt < 8; kt++) {
            uint32_t a0 = Ps[(rowA)     * KSTR + kt * 8 + t];
            uint32_t a1 = Ps[(rowA + 8) * KSTR + kt * 8 + t];
            uint32_t a2 = Ps[(rowA)     * KSTR + kt * 8 + t + 4];
            uint32_t a3 = Ps[(rowA + 8) * KSTR + kt * 8 + t + 4];
#pragma unroll
            for (int dt = 0; dt < 8; dt++) {
                uint32_t b0 = Vs[(kt * 8 + t)     * VSTR + dt * 8 + g];
                uint32_t b1 = Vs[(kt * 8 + t + 4) * VSTR + dt * 8 + g];
                mma_tf32(o[dt], a0, a1, a2, a3, b0, b1);
            }
        }
    }

    float lA = l[0];
    lA += __shfl_xor_sync(0xffffffffu, lA, 1);
    lA += __shfl_xor_sync(0xffffffffu, lA, 2);
    float lB = l[1];
    lB += __shfl_xor_sync(0xffffffffu, lB, 1);
    lB += __shfl_xor_sync(0xffffffffu, lB, 2);
    const float iA = 1.f / lA, iB = 1.f / lB;

    const int h  = bh & 7;
    const int b_ = bh >> 3;
    float* yA = g_y + ((size_t)(b_ * TT + qA))     * CC + h * 64;
    float* yB = g_y + ((size_t)(b_ * TT + qA + 8)) * CC + h * 64;
#pragma unroll
    for (int dt = 0; dt < 8; dt++) {
        *(float2*)(yA + dt * 8 + 2 * t) = make_float2(o[dt][0] * iA, o[dt][1] * iA);
        *(float2*)(yB + dt * 8 + 2 * t) = make_float2(o[dt][2] * iB, o[dt][3] * iB);
    }
}

// ---------------------------------------------------------------------------

extern "C" void kernel_launch(void* const* d_in, const int* in_sizes, int n_in,
                              void* d_out, int out_size)
{
    const float* x    = (const float*)d_in[0];
    const float* Wq   = (const float*)d_in[1];
    const float* Wk   = (const float*)d_in[2];
    const float* Wv   = (const float*)d_in[3];
    const float* Wout = (const float*)d_in[4];
    float* out = (float*)d_out;

    cudaFuncSetAttribute(flash_tc, cudaFuncAttributeMaxDynamicSharedMemorySize,
                         FLASH_SMEM);
    cudaFuncSetAttribute(gemm_qkv_tc, cudaFuncAttributeMaxDynamicSharedMemorySize,
                         GEMM_SMEM);
    cudaFuncSetAttribute(gemm_out_tc, cudaFuncAttributeMaxDynamicSharedMemorySize,
                         GEMM_SMEM);

    gemm_qkv_tc<<<dim3(CC / 128, MM / 128, 3), 256, GEMM_SMEM>>>(x, Wq, Wk, Wv);
    flash_tc<<<dim3(TT / 64, BB * HH), 128, FLASH_SMEM>>>();
    gemm_out_tc<<<dim3(CC / 128, MM / 128), 256, GEMM_SMEM>>>(Wout, out);
}

// round 6
// speedup vs baseline: 7.4267x; 1.2374x over previous
#include <cuda_runtime.h>
#include <cuda_bf16.h>
#include <math.h>
#include <stdint.h>

// Problem constants
#define BB 2
#define HH 8
#define TT 4096
#define DD 64
#define CC 512
#define MM (BB*TT)   // 8192

// Scratch (device globals: allocation-free)
__device__ float g_q[BB*HH*TT*DD];   // [b,h,t,d]
__device__ float g_k[BB*HH*TT*DD];
__device__ float g_v[BB*HH*TT*DD];
__device__ float g_y[BB*TT*CC];      // [b,t,c]  attention output before Wout

// ---------------------------------------------------------------------------
// Helpers
// ---------------------------------------------------------------------------

__device__ __forceinline__ uint32_t f2tf(float f) {
    uint32_t u;
    asm("cvt.rna.tf32.f32 %0, %1;" : "=r"(u) : "f"(f));
    return u;
}
__device__ __forceinline__ float ex2(float x) {
    float y;
    asm("ex2.approx.ftz.f32 %0, %1;" : "=f"(y) : "f"(x));
    return y;
}
__device__ __forceinline__ void mma_tf32(float c[4],
                                         uint32_t a0, uint32_t a1, uint32_t a2, uint32_t a3,
                                         uint32_t b0, uint32_t b1) {
    asm volatile(
        "mma.sync.aligned.m16n8k8.row.col.f32.tf32.tf32.f32 "
        "{%0,%1,%2,%3}, {%4,%5,%6,%7}, {%8,%9}, {%0,%1,%2,%3};"
        : "+f"(c[0]), "+f"(c[1]), "+f"(c[2]), "+f"(c[3])
        : "r"(a0), "r"(a1), "r"(a2), "r"(a3), "r"(b0), "r"(b1));
}
__device__ __forceinline__ void mma_bf16(float c[4],
                                         uint32_t a0, uint32_t a1, uint32_t a2, uint32_t a3,
                                         uint32_t b0, uint32_t b1) {
    asm volatile(
        "mma.sync.aligned.m16n8k16.row.col.f32.bf16.bf16.f32 "
        "{%0,%1,%2,%3}, {%4,%5,%6,%7}, {%8,%9}, {%0,%1,%2,%3};"
        : "+f"(c[0]), "+f"(c[1]), "+f"(c[2]), "+f"(c[3])
        : "r"(a0), "r"(a1), "r"(a2), "r"(a3), "r"(b0), "r"(b1));
}

// bf16 hi/lo split of a float pair; hi+lo captures ~16 mantissa bits.
__device__ __forceinline__ void split2_bf16(float x, float y, uint32_t& hi, uint32_t& lo) {
    __nv_bfloat162 h = __floats2bfloat162_rn(x, y);
    float rx = x - __bfloat162float(h.x);
    float ry = y - __bfloat162float(h.y);
    __nv_bfloat162 l = __floats2bfloat162_rn(rx, ry);
    hi = *(uint32_t*)&h;
    lo = *(uint32_t*)&l;
}

// ---------------------------------------------------------------------------
// Tensor-core split-bf16 GEMM: C[m,o] = sum_c X[m,c] * W[o,c]
// CTA 128x128, BK=32, 256 threads (8 warps, 4x2 warp grid, 32x64 warp tile).
// Smem rows of 16 u32 (bf16x2), stride GSTR=20 u32 -> conflict-free frags.
// 3-term: hi*hi + lo*hi + hi*lo (drop lo*lo ~2^-18).
// ---------------------------------------------------------------------------

#define GSTR 20
#define GEMM_SMEM (4 * 128 * GSTR * (int)sizeof(uint32_t))   // 40960 B

__device__ __forceinline__ void gemm_mainloop(const float* __restrict__ X,
                                              const float* __restrict__ W,
                                              int m0, int n0,
                                              uint32_t* Ah, uint32_t* Al,
                                              uint32_t* Bh, uint32_t* Bl,
                                              float acc[2][8][4])
{
    const int tid  = threadIdx.x;
    const int w    = tid >> 5;
    const int lane = tid & 31;
    const int g    = lane >> 2;
    const int t    = lane & 3;
    const int wm   = w >> 1;            // 0..3 : rows wm*32..+31
    const int wn   = w & 1;             // 0..1 : cols wn*64..+63

    // loader: thread -> row lr = tid>>1, 16 consecutive floats at col (tid&1)*16
    const int lr  = tid >> 1;
    const int lcf = (tid & 1) * 16;     // float col
    const int lcu = (tid & 1) * 8;      // u32 (bf16x2) col
    const float* Xg = X + (m0 + lr) * CC + lcf;
    const float* Wg = W + (n0 + lr) * CC + lcf;

#pragma unroll
    for (int mt = 0; mt < 2; mt++)
#pragma unroll
        for (int nt = 0; nt < 8; nt++)
#pragma unroll
            for (int k = 0; k < 4; k++) acc[mt][nt][k] = 0.f;

    for (int k0 = 0; k0 < CC; k0 += 32) {
        float4 av[4], bv[4];
#pragma unroll
        for (int i = 0; i < 4; i++) {
            av[i] = *(const float4*)(Xg + k0 + i * 4);
            bv[i] = *(const float4*)(Wg + k0 + i * 4);
        }
        __syncthreads();   // previous-iter frag reads done
#pragma unroll
        for (int i = 0; i < 4; i++) {
            uint32_t h0, l0, h1, l1;
            split2_bf16(av[i].x, av[i].y, h0, l0);
            split2_bf16(av[i].z, av[i].w, h1, l1);
            *(uint2*)&Ah[lr * GSTR + lcu + i * 2] = make_uint2(h0, h1);
            *(uint2*)&Al[lr * GSTR + lcu + i * 2] = make_uint2(l0, l1);
            split2_bf16(bv[i].x, bv[i].y, h0, l0);
            split2_bf16(bv[i].z, bv[i].w, h1, l1);
            *(uint2*)&Bh[lr * GSTR + lcu + i * 2] = make_uint2(h0, h1);
            *(uint2*)&Bl[lr * GSTR + lcu + i * 2] = make_uint2(l0, l1);
        }
        __syncthreads();

#pragma unroll
        for (int ks = 0; ks < 2; ks++) {       // two k16 steps per BK=32
            const int kb = ks * 8;
            uint32_t ah[2][4], al[2][4], b[8][2];
#pragma unroll
            for (int mt = 0; mt < 2; mt++) {
                int r = wm * 32 + mt * 16 + g;
                ah[mt][0] = Ah[(r)     * GSTR + kb + t];
                ah[mt][1] = Ah[(r + 8) * GSTR + kb + t];
                ah[mt][2] = Ah[(r)     * GSTR + kb + t + 4];
                ah[mt][3] = Ah[(r + 8) * GSTR + kb + t + 4];
                al[mt][0] = Al[(r)     * GSTR + kb + t];
                al[mt][1] = Al[(r + 8) * GSTR + kb + t];
                al[mt][2] = Al[(r)     * GSTR + kb + t + 4];
                al[mt][3] = Al[(r + 8) * GSTR + kb + t + 4];
            }
            // B-hi frags for all nt
#pragma unroll
            for (int nt = 0; nt < 8; nt++) {
                int cn = wn * 64 + nt * 8 + g;
                b[nt][0] = Bh[cn * GSTR + kb + t];
                b[nt][1] = Bh[cn * GSTR + kb + t + 4];
            }
            // hi*hi
#pragma unroll
            for (int nt = 0; nt < 8; nt++)
#pragma unroll
                for (int mt = 0; mt < 2; mt++)
                    mma_bf16(acc[mt][nt], ah[mt][0], ah[mt][1], ah[mt][2], ah[mt][3],
                             b[nt][0], b[nt][1]);
            // lo*hi
#pragma unroll
            for (int nt = 0; nt < 8; nt++)
#pragma unroll
                for (int mt = 0; mt < 2; mt++)
                    mma_bf16(acc[mt][nt], al[mt][0], al[mt][1], al[mt][2], al[mt][3],
                             b[nt][0], b[nt][1]);
            // hi*lo (reload b regs with B-lo)
#pragma unroll
            for (int nt = 0; nt < 8; nt++) {
                int cn = wn * 64 + nt * 8 + g;
                b[nt][0] = Bl[cn * GSTR + kb + t];
                b[nt][1] = Bl[cn * GSTR + kb + t + 4];
            }
#pragma unroll
            for (int nt = 0; nt < 8; nt++)
#pragma unroll
                for (int mt = 0; mt < 2; mt++)
                    mma_bf16(acc[mt][nt], ah[mt][0], ah[mt][1], ah[mt][2], ah[mt][3],
                             b[nt][0], b[nt][1]);
        }
    }
}

// QKV projections, epilogue scatters into [b,h,t,d]
__global__ __launch_bounds__(256, 2) void gemm_qkv_tc(const float* __restrict__ X,
                                                      const float* __restrict__ Wq,
                                                      const float* __restrict__ Wk,
                                                      const float* __restrict__ Wv)
{
    const float* W   = (blockIdx.z == 0) ? Wq : (blockIdx.z == 1) ? Wk : Wv;
    float*       Out = (blockIdx.z == 0) ? g_q : (blockIdx.z == 1) ? g_k : g_v;

    extern __shared__ uint32_t sm[];
    uint32_t* Ah = sm;
    uint32_t* Al = Ah + 128 * GSTR;
    uint32_t* Bh = Al + 128 * GSTR;
    uint32_t* Bl = Bh + 128 * GSTR;

    const int m0 = blockIdx.y * 128, n0 = blockIdx.x * 128;
    float acc[2][8][4];
    gemm_mainloop(X, W, m0, n0, Ah, Al, Bh, Bl, acc);

    const int lane = threadIdx.x & 31;
    const int w    = threadIdx.x >> 5;
    const int g = lane >> 2, t = lane & 3;
    const int wm = w >> 1, wn = w & 1;

#pragma unroll
    for (int mt = 0; mt < 2; mt++) {
        int row = m0 + wm * 32 + mt * 16 + g;
        int b_  = row >> 12;
        int tr  = row & 4095;
#pragma unroll
        for (int nt = 0; nt < 8; nt++) {
            int col = n0 + wn * 64 + nt * 8 + 2 * t;
            int h = col >> 6, d = col & 63;
            float* base = Out + (((size_t)(b_ * HH + h) * TT) + tr) * DD + d;
            *(float2*)base            = make_float2(acc[mt][nt][0], acc[mt][nt][1]);
            *(float2*)(base + 8 * DD) = make_float2(acc[mt][nt][2], acc[mt][nt][3]);
        }
    }
}

// Output projection, plain row-major epilogue
__global__ __launch_bounds__(256, 2) void gemm_out_tc(const float* __restrict__ W,
                                                      float* __restrict__ OutP)
{
    extern __shared__ uint32_t sm[];
    uint32_t* Ah = sm;
    uint32_t* Al = Ah + 128 * GSTR;
    uint32_t* Bh = Al + 128 * GSTR;
    uint32_t* Bl = Bh + 128 * GSTR;

    const int m0 = blockIdx.y * 128, n0 = blockIdx.x * 128;
    float acc[2][8][4];
    gemm_mainloop(g_y, W, m0, n0, Ah, Al, Bh, Bl, acc);

    const int lane = threadIdx.x & 31;
    const int w    = threadIdx.x >> 5;
    const int g = lane >> 2, t = lane & 3;
    const int wm = w >> 1, wn = w & 1;

#pragma unroll
    for (int mt = 0; mt < 2; mt++) {
        int row = m0 + wm * 32 + mt * 16 + g;
#pragma unroll
        for (int nt = 0; nt < 8; nt++) {
            int col = n0 + wn * 64 + nt * 8 + 2 * t;
            float* base = OutP + (size_t)row * CC + col;
            *(float2*)base            = make_float2(acc[mt][nt][0], acc[mt][nt][1]);
            *(float2*)(base + 8 * CC) = make_float2(acc[mt][nt][2], acc[mt][nt][3]);
        }
    }
}

// ---------------------------------------------------------------------------
// Tensor-core flash attention (tf32 mma.sync m16n8k8).
// CTA = 128 threads = 4 warps; 128-query tile (32 rows/warp, mt=2);
// 64-key tiles. B-fragments (K and V) reused across the 2 m-tiles.
// ---------------------------------------------------------------------------

#define KSTR 68
#define VSTR 72
// Q:128 rows, K:64, P:128, V:64
#define FLASH_SMEM ((128*KSTR + 64*KSTR + 128*KSTR + 64*VSTR) * (int)sizeof(uint32_t)) // 105472

__global__ __launch_bounds__(128) void flash_tc()
{
    const int bh    = blockIdx.y;
    const int qtile = gridDim.x - 1 - blockIdx.x;   // long tiles launch first
    const int q0    = qtile * 128;

    const float* Qg = g_q + (size_t)bh * TT * DD;
    const float* Kg = g_k + (size_t)bh * TT * DD;
    const float* Vg = g_v + (size_t)bh * TT * DD;

    extern __shared__ uint32_t smu[];
    uint32_t* Qs = smu;                    // 128 x KSTR
    uint32_t* Ks = Qs + 128 * KSTR;        // 64 x KSTR
    uint32_t* Ps = Ks + 64 * KSTR;         // 128 x KSTR
    uint32_t* Vs = Ps + 128 * KSTR;        // 64 x VSTR

    const int tid  = threadIdx.x;
    const int w    = tid >> 5;             // warp 0..3 -> rows w*32..w*32+31
    const int lane = tid & 31;
    const int g    = lane >> 2;
    const int t    = lane & 3;

    // Load + convert Q tile (128x64) to tf32
    for (int i = tid; i < 2048; i += 128) {
        int r = i >> 4, c4 = (i & 15) * 4;
        float4 v = *(const float4*)(Qg + (q0 + r) * DD + c4);
        uint32_t* p = &Qs[r * KSTR + c4];
        p[0] = f2tf(v.x); p[1] = f2tf(v.y); p[2] = f2tf(v.z); p[3] = f2tf(v.w);
    }

    float m[4], l[4];                      // [mt*2 + half]
#pragma unroll
    for (int i = 0; i < 4; i++) { m[i] = -INFINITY; l[i] = 0.f; }
    float o[2][8][4];
#pragma unroll
    for (int mt = 0; mt < 2; mt++)
#pragma unroll
        for (int dt = 0; dt < 8; dt++)
#pragma unroll
            for (int k = 0; k < 4; k++) o[mt][dt][k] = 0.f;

    const float SC = 0.125f * 1.4426950408889634f;   // 1/sqrt(64) * log2(e)

    const int ntiles = 2 * qtile + 2;
    for (int jt = 0; jt < ntiles; jt++) {
        const int j0 = jt * 64;
        __syncthreads();   // prior-iter readers done (and Q stores on jt==0)

        // Load + convert K,V tiles (64x64 each)
        for (int i = tid; i < 1024; i += 128) {
            int r = i >> 4, c4 = (i & 15) * 4;
            float4 kv = *(const float4*)(Kg + (j0 + r) * DD + c4);
            float4 vv = *(const float4*)(Vg + (j0 + r) * DD + c4);
            uint32_t* pk = &Ks[r * KSTR + c4];
            pk[0] = f2tf(kv.x); pk[1] = f2tf(kv.y); pk[2] = f2tf(kv.z); pk[3] = f2tf(kv.w);
            uint32_t* pv = &Vs[r * VSTR + c4];
            pv[0] = f2tf(vv.x); pv[1] = f2tf(vv.y); pv[2] = f2tf(vv.z); pv[3] = f2tf(vv.w);
        }
        __syncthreads();

        // ---- S = Q K^T
        float c[2][8][4];
#pragma unroll
        for (int mt = 0; mt < 2; mt++)
#pragma unroll
            for (int nt = 0; nt < 8; nt++)
#pragma unroll
                for (int k = 0; k < 4; k++) c[mt][nt][k] = 0.f;

#pragma unroll
        for (int ks = 0; ks < 8; ks++) {
            uint32_t a[2][4];
#pragma unroll
            for (int mt = 0; mt < 2; mt++) {
                int r = w * 32 + mt * 16 + g;
                a[mt][0] = Qs[(r)     * KSTR + ks * 8 + t];
                a[mt][1] = Qs[(r + 8) * KSTR + ks * 8 + t];
                a[mt][2] = Qs[(r)     * KSTR + ks * 8 + t + 4];
                a[mt][3] = Qs[(r + 8) * KSTR + ks * 8 + t + 4];
            }
#pragma unroll
            for (int nt = 0; nt < 8; nt++) {
                uint32_t b0 = Ks[(nt * 8 + g) * KSTR + ks * 8 + t];
                uint32_t b1 = Ks[(nt * 8 + g) * KSTR + ks * 8 + t + 4];
#pragma unroll
                for (int mt = 0; mt < 2; mt++)
                    mma_tf32(c[mt][nt], a[mt][0], a[mt][1], a[mt][2], a[mt][3], b0, b1);
            }
        }

        // ---- softmax (log2 domain), causal mask on diagonal tiles
        const bool diag = (jt >= 2 * qtile);
#pragma unroll
        for (int mt = 0; mt < 2; mt++) {
            const int rowA = w * 32 + mt * 16 + g;
            const int qA   = q0 + rowA;
            float mA = -INFINITY, mB = -INFINITY;
#pragma unroll
            for (int nt = 0; nt < 8; nt++) {
                int j = j0 + nt * 8 + 2 * t;
                float s0 = c[mt][nt][0] * SC, s1 = c[mt][nt][1] * SC;
                float s2 = c[mt][nt][2] * SC, s3 = c[mt][nt][3] * SC;
                if (diag) {
                    if (j     > qA)     s0 = -1e30f;
                    if (j + 1 > qA)     s1 = -1e30f;
                    if (j     > qA + 8) s2 = -1e30f;
                    if (j + 1 > qA + 8) s3 = -1e30f;
                }
                c[mt][nt][0] = s0; c[mt][nt][1] = s1;
                c[mt][nt][2] = s2; c[mt][nt][3] = s3;
                mA = fmaxf(mA, fmaxf(s0, s1));
                mB = fmaxf(mB, fmaxf(s2, s3));
            }
            mA = fmaxf(mA, __shfl_xor_sync(0xffffffffu, mA, 1));
            mA = fmaxf(mA, __shfl_xor_sync(0xffffffffu, mA, 2));
            mB = fmaxf(mB, __shfl_xor_sync(0xffffffffu, mB, 1));
            mB = fmaxf(mB, __shfl_xor_sync(0xffffffffu, mB, 2));

            float mnA = fmaxf(m[2 * mt], mA), mnB = fmaxf(m[2 * mt + 1], mB);
            float corrA = ex2(m[2 * mt] - mnA), corrB = ex2(m[2 * mt + 1] - mnB);
            m[2 * mt] = mnA; m[2 * mt + 1] = mnB;

            float lpA = 0.f, lpB = 0.f;
#pragma unroll
            for (int nt = 0; nt < 8; nt++) {
                float p0 = ex2(c[mt][nt][0] - mnA), p1 = ex2(c[mt][nt][1] - mnA);
                float p2 = ex2(c[mt][nt][2] - mnB), p3 = ex2(c[mt][nt][3] - mnB);
                lpA += p0 + p1;  lpB += p2 + p3;
                *(uint2*)&Ps[(rowA)     * KSTR + nt * 8 + 2 * t] =
                    make_uint2(f2tf(p0), f2tf(p1));
                *(uint2*)&Ps[(rowA + 8) * KSTR + nt * 8 + 2 * t] =
                    make_uint2(f2tf(p2), f2tf(p3));
            }
            l[2 * mt]     = l[2 * mt]     * corrA + lpA;
            l[2 * mt + 1] = l[2 * mt + 1] * corrB + lpB;
#pragma unroll
            for (int dt = 0; dt < 8; dt++) {
                o[mt][dt][0] *= corrA; o[mt][dt][1] *= corrA;
                o[mt][dt][2] *= corrB; o[mt][dt][3] *= corrB;
            }
        }
        __syncwarp();   // P rows are warp-private

        // ---- O += P V
#pragma unroll
        for (int kt = 0; kt < 8; kt++) {
            uint32_t a[2][4];
#pragma unroll
            for (int mt = 0; mt < 2; mt++) {
                int r = w * 32 + mt * 16 + g;
                a[mt][0] = Ps[(r)     * KSTR + kt * 8 + t];
                a[mt][1] = Ps[(r + 8) * KSTR + kt * 8 + t];
                a[mt][2] = Ps[(r)     * KSTR + kt * 8 + t + 4];
                a[mt][3] = Ps[(r + 8) * KSTR + kt * 8 + t + 4];
            }
#pragma unroll
            for (int dt = 0; dt < 8; dt++) {
                uint32_t b0 = Vs[(kt * 8 + t)     * VSTR + dt * 8 + g];
                uint32_t b1 = Vs[(kt * 8 + t + 4) * VSTR + dt * 8 + g];
#pragma unroll
                for (int mt = 0; mt < 2; mt++)
                    mma_tf32(o[mt][dt], a[mt][0], a[mt][1], a[mt][2], a[mt][3], b0, b1);
            }
        }
    }

    // ---- normalize + write to g_y [b,t,c], c = h*64 + d
    const int h  = bh & 7;
    const int b_ = bh >> 3;
#pragma unroll
    for (int mt = 0; mt < 2; mt++) {
        float lA = l[2 * mt];
        lA += __shfl_xor_sync(0xffffffffu, lA, 1);
        lA += __shfl_xor_sync(0xffffffffu, lA, 2);
        float lB = l[2 * mt + 1];
        lB += __shfl_xor_sync(0xffffffffu, lB, 1);
        lB += __shfl_xor_sync(0xffffffffu, lB, 2);
        const float iA = 1.f / lA, iB = 1.f / lB;

        const int qA = q0 + w * 32 + mt * 16 + g;
        float* yA = g_y + ((size_t)(b_ * TT + qA))     * CC + h * 64;
        float* yB = g_y + ((size_t)(b_ * TT + qA + 8)) * CC + h * 64;
#pragma unroll
        for (int dt = 0; dt < 8; dt++) {
            *(float2*)(yA + dt * 8 + 2 * t) =
                make_float2(o[mt][dt][0] * iA, o[mt][dt][1] * iA);
            *(float2*)(yB + dt * 8 + 2 * t) =
                make_float2(o[mt][dt][2] * iB, o[mt][dt][3] * iB);
        }
    }
}

// ---------------------------------------------------------------------------

extern "C" void kernel_launch(void* const* d_in, const int* in_sizes, int n_in,
                              void* d_out, int out_size)
{
    const float* x    = (const float*)d_in[0];
    const float* Wq   = (const float*)d_in[1];
    const float* Wk   = (const float*)d_in[2];
    const float* Wv   = (const float*)d_in[3];
    const float* Wout = (const float*)d_in[4];
    float* out = (float*)d_out;

    cudaFuncSetAttribute(flash_tc, cudaFuncAttributeMaxDynamicSharedMemorySize,
                         FLASH_SMEM);
    cudaFuncSetAttribute(gemm_qkv_tc, cudaFuncAttributeMaxDynamicSharedMemorySize,
                         GEMM_SMEM);
    cudaFuncSetAttribute(gemm_out_tc, cudaFuncAttributeMaxDynamicSharedMemorySize,
                         GEMM_SMEM);

    gemm_qkv_tc<<<dim3(CC / 128, MM / 128, 3), 256, GEMM_SMEM>>>(x, Wq, Wk, Wv);
    flash_tc<<<dim3(TT / 128, BB * HH), 128, FLASH_SMEM>>>();
    gemm_out_tc<<<dim3(CC / 128, MM / 128), 256, GEMM_SMEM>>>(Wout, out);
}